// round 1
// baseline (speedup 1.0000x reference)
#include <cuda_runtime.h>
#include <cstdint>

#define BB   512
#define NN   256
#define NVT  32
#define HS   128
#define G3   384   // 3*HS
#define NZ   64
#define VT   16    // v-tile per thread group in pass 2

// ---------- precomputed tables (device globals: no allocation allowed) ----------
__device__ float g_tbl[NVT * HS];   // gated message table  tbl[t][h]
__device__ float g_M[NVT * G3];     // M[t][g] = sum_h tbl[t][h] * W_hh[g][h]
__device__ float g_gi[NVT * G3];    // gi[t][g] = W_ih[g][t] + b_ih[g]

// ---------- kernel A: build tables ----------
__global__ void dvae_tables_kernel(const float* __restrict__ W_ih,
                                   const float* __restrict__ W_hh,
                                   const float* __restrict__ b_ih,
                                   const float* __restrict__ Wg,
                                   const float* __restrict__ bg,
                                   const float* __restrict__ Wm) {
    __shared__ float s_tbl[HS];
    int t = blockIdx.x;      // 0..31
    int g = threadIdx.x;     // 0..383
    if (g < HS) {
        float x  = Wg[g * NVT + t] + bg[g];
        float sg = __fdividef(1.f, 1.f + __expf(-x));
        float v  = sg * Wm[g * NVT + t];
        s_tbl[g] = v;
        g_tbl[t * HS + g] = v;
    }
    __syncthreads();
    float acc = 0.f;
    #pragma unroll 8
    for (int h = 0; h < HS; h++) acc += s_tbl[h] * W_hh[g * HS + h];
    g_M[t * G3 + g]  = acc;
    g_gi[t * G3 + g] = W_ih[g * NVT + t] + b_ih[g];
}

// ---------- kernel B: per-batch histogram + GRU + heads ----------
// smem layout (bytes):
//   s_M    : 32*384*4 = 49152
//   s_tbl  : 32*128*4 = 16384
//   s_cnt  : 32*256*4 = 32768   (int during pass1, float after in-place cvt)
//   s_type : 256*4    = 1024
//   s_hg   : 128*4    = 512
#define SMEM_BYTES (49152 + 16384 + 32768 + 1024 + 512)

__device__ __forceinline__ float fast_sigmoid(float x) {
    return __fdividef(1.f, 1.f + __expf(-x));
}
__device__ __forceinline__ float fast_tanh(float x) {
    // tanh(x) = 1 - 2/(exp(2x)+1); exact limits at +-inf via IEEE semantics
    float e = __expf(2.f * x);
    return 1.f - __fdividef(2.f, e + 1.f);
}

__global__ __launch_bounds__(256, 2)
void dvae_main_kernel(const int* __restrict__ node_types,
                      const int* __restrict__ adj,
                      const float* __restrict__ b_hh,
                      const float* __restrict__ W1, const float* __restrict__ b1,
                      const float* __restrict__ W2, const float* __restrict__ b2,
                      float* __restrict__ out) {
    extern __shared__ char smem[];
    float* s_M    = (float*)smem;                         // [32][384]
    float* s_tbl  = s_M + NVT * G3;                       // [32][128]
    float* s_cnt  = s_tbl + NVT * HS;                     // [32][256]
    int*   s_cnti = (int*)s_cnt;
    int*   s_type = (int*)(s_cnt + NVT * NN);             // [256]
    float* s_hg   = (float*)(s_type + NN);                // [128]

    const int b   = blockIdx.x;
    const int tid = threadIdx.x;

    // stage tables + types, zero counters
    for (int i = tid; i < NVT * G3; i += 256) s_M[i] = g_M[i];
    for (int i = tid; i < NVT * HS; i += 256) s_tbl[i] = g_tbl[i];
    s_type[tid] = node_types[b * NN + tid];
    for (int i = tid; i < NVT * NN; i += 256) s_cnti[i] = 0;
    __syncthreads();

    // ---- pass 1: per-(v,type) predecessor histogram. thread = v ----
    {
        const int* arow = adj + (size_t)b * NN * NN;
        const int v = tid;
        #pragma unroll 4
        for (int u = 0; u < NN; u++) {
            int a = __ldg(arow + u * NN + v);   // coalesced over v
            int t = s_type[u];                  // warp-uniform broadcast
            s_cnti[t * NN + v] += a;            // bank-conflict-free ([t][v])
        }
    }
    __syncthreads();
    // in-place int -> float
    for (int i = tid; i < NVT * NN; i += 256)
        s_cnti[i] = __float_as_int((float)s_cnti[i]);
    __syncthreads();

    // ---- pass 2: gh = cnt@M (+b_hh), Hpre = cnt@tbl, GRU, graph sum ----
    const int hh  = tid & 127;   // h index
    const int grp = tid >> 7;    // which v-subtile (0/1)
    const float bhr = b_hh[hh];
    const float bhz = b_hh[HS + hh];
    const float bhn = b_hh[2 * HS + hh];
    float hg = 0.f;

    for (int v0 = 0; v0 < NN; v0 += 2 * VT) {
        const int vb = v0 + grp * VT;
        float gr[VT], gz[VT], gn[VT], hp[VT];
        #pragma unroll
        for (int i = 0; i < VT; i++) { gr[i] = bhr; gz[i] = bhz; gn[i] = bhn; hp[i] = 0.f; }

        #pragma unroll 4
        for (int t = 0; t < NVT; t++) {
            const float mr = s_M[t * G3 + hh];
            const float mz = s_M[t * G3 + HS + hh];
            const float mn = s_M[t * G3 + 2 * HS + hh];
            const float tb = s_tbl[t * HS + hh];
            const float4* cp = (const float4*)(s_cnt + t * NN + vb);
            #pragma unroll
            for (int i4 = 0; i4 < VT / 4; i4++) {
                float4 c4 = cp[i4];               // broadcast, 4 v's per LDS.128
                float cc0 = c4.x, cc1 = c4.y, cc2 = c4.z, cc3 = c4.w;
                int i = i4 * 4;
                gr[i+0] += cc0 * mr; gz[i+0] += cc0 * mz; gn[i+0] += cc0 * mn; hp[i+0] += cc0 * tb;
                gr[i+1] += cc1 * mr; gz[i+1] += cc1 * mz; gn[i+1] += cc1 * mn; hp[i+1] += cc1 * tb;
                gr[i+2] += cc2 * mr; gz[i+2] += cc2 * mz; gn[i+2] += cc2 * mn; hp[i+2] += cc2 * tb;
                gr[i+3] += cc3 * mr; gz[i+3] += cc3 * mz; gn[i+3] += cc3 * mn; hp[i+3] += cc3 * tb;
            }
        }

        // GRU epilogue for this v-tile
        #pragma unroll
        for (int i = 0; i < VT; i++) {
            const int v  = vb + i;
            const int tv = s_type[v];
            const float gir = __ldg(&g_gi[tv * G3 + hh]);
            const float giz = __ldg(&g_gi[tv * G3 + HS + hh]);
            const float gin = __ldg(&g_gi[tv * G3 + 2 * HS + hh]);
            float r  = fast_sigmoid(gir + gr[i]);
            float z  = fast_sigmoid(giz + gz[i]);
            float nn = fast_tanh(gin + r * gn[i]);
            float Hv = (1.f - z) * nn + z * hp[i];
            if (v >= 1 && v < NN - 1) hg += Hv;   // graph state: v in [1, N-1)
        }
    }

    // reduce the two v-groups into s_hg[h]
    if (grp == 0) s_hg[hh] = hg;
    __syncthreads();
    if (grp == 1) s_hg[hh] += hg;
    __syncthreads();

    // ---- heads: mu (threads 0..63), logvar (threads 64..127) ----
    if (tid < 2 * NZ) {
        const int j = tid & (NZ - 1);
        const float* W  = (tid < NZ) ? W1 : W2;
        const float* bv = (tid < NZ) ? b1 : b2;
        float acc = bv[j];
        #pragma unroll 8
        for (int h = 0; h < HS; h++) acc += s_hg[h] * W[j * HS + h];
        out[((tid < NZ) ? 0 : BB * NZ) + b * NZ + j] = acc;
    }
}

// ---------- launch ----------
extern "C" void kernel_launch(void* const* d_in, const int* in_sizes, int n_in,
                              void* d_out, int out_size) {
    const int*   node_types = (const int*)  d_in[0];
    const int*   adj        = (const int*)  d_in[1];
    const float* W_ih       = (const float*)d_in[2];
    const float* W_hh       = (const float*)d_in[3];
    const float* b_ih       = (const float*)d_in[4];
    const float* b_hh       = (const float*)d_in[5];
    const float* Wg         = (const float*)d_in[6];
    const float* bg         = (const float*)d_in[7];
    const float* Wm         = (const float*)d_in[8];
    const float* W1         = (const float*)d_in[9];
    const float* b1         = (const float*)d_in[10];
    const float* W2         = (const float*)d_in[11];
    const float* b2         = (const float*)d_in[12];
    float* out = (float*)d_out;

    cudaFuncSetAttribute(dvae_main_kernel,
                         cudaFuncAttributeMaxDynamicSharedMemorySize, SMEM_BYTES);

    dvae_tables_kernel<<<NVT, G3>>>(W_ih, W_hh, b_ih, Wg, bg, Wm);
    dvae_main_kernel<<<BB, 256, SMEM_BYTES>>>(node_types, adj, b_hh,
                                              W1, b1, W2, b2, out);
}